// round 12
// baseline (speedup 1.0000x reference)
#include <cuda_runtime.h>

#define IN_CH 64
#define HIDDEN 16
#define OUT_CH 8
#define N_NODES_MAX 50000
#define N_EDGES_MAX 800000
#define NTHREADS 256
#define NBLOCKS 592   // 148 SMs x 4 blocks, co-resident via __launch_bounds__(256,4)

// Scratch (allocation-free rule: __device__ globals). +1 dummy sink row.
__device__ int   g_degi[N_NODES_MAX + 1];        // in-degree (int), sink last
__device__ int   g_off [N_NODES_MAX + 1];        // CSR row offsets
__device__ int   g_cur [N_NODES_MAX + 1];        // build cursors
__device__ int2  g_edges[N_EDGES_MAX];           // decoded (src,dst); invalid -> sink
__device__ int2  g_csre [N_EDGES_MAX + 8];       // dst-sorted (src,dst) slots (+pad)
__device__ float g_p1[(N_NODES_MAX + 1) * HIDDEN];
__device__ float g_r1[N_NODES_MAX * HIDDEN];
__device__ float g_s1[(N_NODES_MAX + 1) * HIDDEN];
__device__ float g_p2[(N_NODES_MAX + 1) * OUT_CH];
__device__ float g_s2[(N_NODES_MAX + 1) * OUT_CH];
__device__ int           g_bar_count;            // returns to 0 at kernel exit
__device__ volatile int  g_bar_gen;              // monotonic; ok across replays

// Vectorized global reduction (sm_90+). No memory clobber: targets (s1/s2)
// are never read in the same phase, and grid barriers fence across phases.
__device__ __forceinline__ void red_add_v4(float* addr, float4 v) {
    asm volatile("red.global.add.v4.f32 [%0], {%1, %2, %3, %4};"
                 :: "l"(addr), "f"(v.x), "f"(v.y), "f"(v.z), "f"(v.w));
}

__device__ __forceinline__ float4 ldcg4(const float* p) {
    float4 v;
    asm volatile("ld.global.cg.v4.f32 {%0,%1,%2,%3}, [%4];"
                 : "=f"(v.x), "=f"(v.y), "=f"(v.z), "=f"(v.w) : "l"(p));
    return v;
}
__device__ __forceinline__ int ldcg_i(const int* p) {
    int v;
    asm volatile("ld.global.cg.s32 %0, [%1];" : "=r"(v) : "l"(p));
    return v;
}

// Software grid barrier (all NBLOCKS resident by launch_bounds + grid size).
__device__ __forceinline__ void grid_barrier() {
    __syncthreads();
    if (threadIdx.x == 0) {
        int gen = g_bar_gen;
        __threadfence();  // release (gpu scope)
        if (atomicAdd(&g_bar_count, 1) == NBLOCKS - 1) {
            g_bar_count = 0;
            __threadfence();
            g_bar_gen = gen + 1;
        } else {
            while (g_bar_gen == gen) __nanosleep(64);
        }
        __threadfence();  // acquire
    }
    __syncthreads();
}

__global__ void __launch_bounds__(NTHREADS, 4)
fused_sage_kernel(const float* __restrict__ x,
                  const float* __restrict__ W1l,
                  const float* __restrict__ W1r,
                  const float* __restrict__ b1,
                  const float* __restrict__ W2l,
                  const float* __restrict__ W2r,
                  const float* __restrict__ b2,
                  const int*   __restrict__ ei,
                  int n_nodes, int n_edges, int n_words,
                  float* __restrict__ out) {
    __shared__ float sW1l[HIDDEN * IN_CH];
    __shared__ float sW1r[HIDDEN * IN_CH];
    __shared__ float sb1[HIDDEN];
    __shared__ float sW2l[OUT_CH * HIDDEN];
    __shared__ float sW2r[OUT_CH * HIDDEN];
    __shared__ float sb2[OUT_CH];
    __shared__ int   sscan[NTHREADS];

    const int T = NBLOCKS * NTHREADS;
    const int t = blockIdx.x * NTHREADS + threadIdx.x;
    const int padded = (n_edges + 7) & ~7;

    for (int i = threadIdx.x; i < HIDDEN * IN_CH; i += NTHREADS) {
        sW1l[i] = W1l[i];
        sW1r[i] = W1r[i];
    }
    for (int i = threadIdx.x; i < OUT_CH * HIDDEN; i += NTHREADS) {
        sW2l[i] = W2l[i];
        sW2r[i] = W2r[i];
    }
    if (threadIdx.x < HIDDEN) sb1[threadIdx.x] = b1[threadIdx.x];
    if (threadIdx.x < OUT_CH) sb2[threadIdx.x] = b2[threadIdx.x];

    // Parallel dtype detect: int64 little-endian indices in [0,50000) -> all
    // odd int32 words are 0; int32 -> random indices, never all zero over 256.
    int w = 2 * threadIdx.x + 1;
    int mine = (w < n_words) ? (ei[w] != 0) : 0;
    const int is64 = __syncthreads_or(mine) ? 0 : 1;

    // ---- Phase 0: zero degree counters + s1; pad CSR tail; sink rows -----
    for (int i = t; i < n_nodes + 1; i += T) g_degi[i] = 0;
    for (int i = t; i < (n_nodes + 1) * HIDDEN; i += T) g_s1[i] = 0.0f;
    if (t < 8 && n_edges + t < N_EDGES_MAX + 8)
        g_csre[n_edges + t] = make_int2(N_NODES_MAX, N_NODES_MAX);
    if (t < 4)
        *reinterpret_cast<float4*>(&g_p1[N_NODES_MAX * HIDDEN + t * 4]) =
            make_float4(0.f, 0.f, 0.f, 0.f);
    if (t >= 4 && t < 6)
        *reinterpret_cast<float4*>(&g_p2[N_NODES_MAX * OUT_CH + (t - 4) * 4]) =
            make_float4(0.f, 0.f, 0.f, 0.f);
    grid_barrier();

    // ---- Phase 1: gemm1 -> p1, r1  ||  decode edges + degree count -------
    for (int idx = t; idx < n_nodes * 4; idx += T) {
        int n = idx >> 2;
        int q = idx & 3;
        int h0 = q * 4;
        float accl[4], accr[4];
#pragma unroll
        for (int j = 0; j < 4; j++) { accl[j] = 0.0f; accr[j] = sb1[h0 + j]; }
        const float4* xr = reinterpret_cast<const float4*>(x + (size_t)n * IN_CH);
#pragma unroll
        for (int c4 = 0; c4 < IN_CH / 4; c4++) {
            float4 v = xr[c4];
#pragma unroll
            for (int j = 0; j < 4; j++) {
                const float* wl = &sW1l[(h0 + j) * IN_CH + c4 * 4];
                const float* wr = &sW1r[(h0 + j) * IN_CH + c4 * 4];
                accl[j] += v.x * wl[0] + v.y * wl[1] + v.z * wl[2] + v.w * wl[3];
                accr[j] += v.x * wr[0] + v.y * wr[1] + v.z * wr[2] + v.w * wr[3];
            }
        }
        *reinterpret_cast<float4*>(&g_p1[n * HIDDEN + h0]) =
            make_float4(accl[0], accl[1], accl[2], accl[3]);
        *reinterpret_cast<float4*>(&g_r1[n * HIDDEN + h0]) =
            make_float4(accr[0], accr[1], accr[2], accr[3]);
    }
    for (int e = t; e < n_edges; e += T) {
        int src, dst;
        if (is64) {
            const int2* p = reinterpret_cast<const int2*>(ei);
            src = p[e].x;
            dst = p[n_edges + e].x;
        } else {
            src = ei[e];
            dst = ei[n_edges + e];
        }
        bool ok = ((unsigned)src < (unsigned)n_nodes) & ((unsigned)dst < (unsigned)n_nodes);
        if (!ok) { src = N_NODES_MAX; dst = N_NODES_MAX; }
        g_edges[e] = make_int2(src, dst);
        atomicAdd(&g_degi[dst], 1);
    }
    grid_barrier();

    // ---- Phase 2: exclusive scan of degrees -> g_off, g_cur (block 0) ----
    if (blockIdx.x == 0) {
        int tid = threadIdx.x;
        int total_rows = n_nodes + 1;
        int chunk = (total_rows + NTHREADS - 1) / NTHREADS;
        int start = tid * chunk;
        int end = start + chunk;
        if (end > total_rows) end = total_rows;
        int s = 0;
        for (int i = start; i < end; i++) s += ldcg_i(&g_degi[i]);
        sscan[tid] = s;
        __syncthreads();
        for (int ofs = 1; ofs < NTHREADS; ofs <<= 1) {
            int v = (tid >= ofs) ? sscan[tid - ofs] : 0;
            __syncthreads();
            sscan[tid] += v;
            __syncthreads();
        }
        int base = (tid == 0) ? 0 : sscan[tid - 1];
        for (int i = start; i < end; i++) {
            g_off[i] = base;
            g_cur[i] = base;
            base += ldcg_i(&g_degi[i]);
        }
    }
    grid_barrier();

    // ---- Phase 3: place edges into dst-sorted slots -----------------------
    for (int e = t; e < n_edges; e += T) {
        int2 ed = g_edges[e];
        int pos = atomicAdd(&g_cur[ed.y], 1);
        g_csre[pos] = ed;
    }
    grid_barrier();

    // ---- Phase 4: layer-1 aggregate, run-compressed (8 slots x 8 ch) -----
    {
        const int items = (padded >> 3) * 2;
        for (int it = t; it < items; it += T) {
            int b = (it >> 1) * 8;
            int q = (it & 1) * 8;
            int4 c0 = *reinterpret_cast<const int4*>(&g_csre[b]);
            int4 c1 = *reinterpret_cast<const int4*>(&g_csre[b + 2]);
            int4 c2 = *reinterpret_cast<const int4*>(&g_csre[b + 4]);
            int4 c3 = *reinterpret_cast<const int4*>(&g_csre[b + 6]);
            int src[8] = {c0.x, c0.z, c1.x, c1.z, c2.x, c2.z, c3.x, c3.z};
            int dst[8] = {c0.y, c0.w, c1.y, c1.w, c2.y, c2.w, c3.y, c3.w};
            float4 a0 = make_float4(0.f, 0.f, 0.f, 0.f);
            float4 a1 = make_float4(0.f, 0.f, 0.f, 0.f);
#pragma unroll
            for (int k = 0; k < 8; k++) {
                const float* pr = &g_p1[src[k] * HIDDEN + q];
                float4 v0 = *reinterpret_cast<const float4*>(pr);
                float4 v1 = *reinterpret_cast<const float4*>(pr + 4);
                a0.x += v0.x; a0.y += v0.y; a0.z += v0.z; a0.w += v0.w;
                a1.x += v1.x; a1.y += v1.y; a1.z += v1.z; a1.w += v1.w;
                bool flush = (k == 7) || (dst[k + 1] != dst[k]);
                if (flush) {
                    float* sp = &g_s1[dst[k] * HIDDEN + q];
                    red_add_v4(sp, a0);
                    red_add_v4(sp + 4, a1);
                    a0 = make_float4(0.f, 0.f, 0.f, 0.f);
                    a1 = make_float4(0.f, 0.f, 0.f, 0.f);
                }
            }
        }
    }
    grid_barrier();

    // ---- Phase 5: layer2: h=relu(s1/deg + r1); p2 = h@W2l^T;
    //      s2 seeded with (h@W2r^T + b2) * deg_eff so phase 7 is a pure scale.
    for (int n = t; n < n_nodes; n += T) {
        float dv = (float)ldcg_i(&g_degi[n]);
        float deg_eff = fmaxf(dv, 1.0f);
        float inv_d = 1.0f / deg_eff;
        float h[HIDDEN];
#pragma unroll
        for (int q = 0; q < HIDDEN / 4; q++) {
            float4 sv = ldcg4(&g_s1[n * HIDDEN + q * 4]);
            float4 rv = *reinterpret_cast<const float4*>(&g_r1[n * HIDDEN + q * 4]);
            h[q * 4 + 0] = fmaxf(sv.x * inv_d + rv.x, 0.0f);
            h[q * 4 + 1] = fmaxf(sv.y * inv_d + rv.y, 0.0f);
            h[q * 4 + 2] = fmaxf(sv.z * inv_d + rv.z, 0.0f);
            h[q * 4 + 3] = fmaxf(sv.w * inv_d + rv.w, 0.0f);
        }
        float accl[OUT_CH], accr[OUT_CH];
#pragma unroll
        for (int o = 0; o < OUT_CH; o++) { accl[o] = 0.0f; accr[o] = sb2[o]; }
#pragma unroll
        for (int c = 0; c < HIDDEN; c++) {
            float v = h[c];
#pragma unroll
            for (int o = 0; o < OUT_CH; o++) {
                accl[o] += v * sW2l[o * HIDDEN + c];
                accr[o] += v * sW2r[o * HIDDEN + c];
            }
        }
        float4* p2o = reinterpret_cast<float4*>(&g_p2[n * OUT_CH]);
        float4* s2o = reinterpret_cast<float4*>(&g_s2[n * OUT_CH]);
        p2o[0] = make_float4(accl[0], accl[1], accl[2], accl[3]);
        p2o[1] = make_float4(accl[4], accl[5], accl[6], accl[7]);
        s2o[0] = make_float4(accr[0] * deg_eff, accr[1] * deg_eff,
                             accr[2] * deg_eff, accr[3] * deg_eff);
        s2o[1] = make_float4(accr[4] * deg_eff, accr[5] * deg_eff,
                             accr[6] * deg_eff, accr[7] * deg_eff);
    }
    if (t < 2)  // s2 sink row must exist for sink REDs in phase 6
        *reinterpret_cast<float4*>(&g_s2[N_NODES_MAX * OUT_CH + t * 4]) =
            make_float4(0.f, 0.f, 0.f, 0.f);
    grid_barrier();

    // ---- Phase 6: layer-2 aggregate, run-compressed (8 slots x 8 ch) -----
    {
        const int items = padded >> 3;
        for (int it = t; it < items; it += T) {
            int b = it * 8;
            int4 c0 = *reinterpret_cast<const int4*>(&g_csre[b]);
            int4 c1 = *reinterpret_cast<const int4*>(&g_csre[b + 2]);
            int4 c2 = *reinterpret_cast<const int4*>(&g_csre[b + 4]);
            int4 c3 = *reinterpret_cast<const int4*>(&g_csre[b + 6]);
            int src[8] = {c0.x, c0.z, c1.x, c1.z, c2.x, c2.z, c3.x, c3.z};
            int dst[8] = {c0.y, c0.w, c1.y, c1.w, c2.y, c2.w, c3.y, c3.w};
            float4 a0 = make_float4(0.f, 0.f, 0.f, 0.f);
            float4 a1 = make_float4(0.f, 0.f, 0.f, 0.f);
#pragma unroll
            for (int k = 0; k < 8; k++) {
                const float* pr = &g_p2[src[k] * OUT_CH];
                float4 v0 = *reinterpret_cast<const float4*>(pr);
                float4 v1 = *reinterpret_cast<const float4*>(pr + 4);
                a0.x += v0.x; a0.y += v0.y; a0.z += v0.z; a0.w += v0.w;
                a1.x += v1.x; a1.y += v1.y; a1.z += v1.z; a1.w += v1.w;
                bool flush = (k == 7) || (dst[k + 1] != dst[k]);
                if (flush) {
                    float* sp = &g_s2[dst[k] * OUT_CH];
                    red_add_v4(sp, a0);
                    red_add_v4(sp + 4, a1);
                    a0 = make_float4(0.f, 0.f, 0.f, 0.f);
                    a1 = make_float4(0.f, 0.f, 0.f, 0.f);
                }
            }
        }
    }
    grid_barrier();

    // ---- Phase 7: out = s2 * inv_deg --------------------------------------
    for (int idx = t; idx < n_nodes * 2; idx += T) {
        int n = idx >> 1;
        int q = idx & 1;
        float dv = (float)ldcg_i(&g_degi[n]);
        float inv_d = 1.0f / fmaxf(dv, 1.0f);
        float4 s = ldcg4(&g_s2[n * OUT_CH + q * 4]);
        float4 o;
        o.x = s.x * inv_d;
        o.y = s.y * inv_d;
        o.z = s.z * inv_d;
        o.w = s.w * inv_d;
        *reinterpret_cast<float4*>(&out[n * OUT_CH + q * 4]) = o;
    }
}

extern "C" void kernel_launch(void* const* d_in, const int* in_sizes, int n_in,
                              void* d_out, int out_size) {
    const float* x   = (const float*)d_in[0];
    const float* W1l = (const float*)d_in[1];
    const float* W1r = (const float*)d_in[2];
    const float* b1  = (const float*)d_in[3];
    const float* W2l = (const float*)d_in[4];
    const float* W2r = (const float*)d_in[5];
    const float* b2  = (const float*)d_in[6];
    const int*   ei  = (const int*)d_in[7];

    int n_nodes = in_sizes[0] / IN_CH;
    int n_edges = in_sizes[7] / 2;
    if (n_nodes > N_NODES_MAX) n_nodes = N_NODES_MAX;
    if (n_edges > N_EDGES_MAX) n_edges = N_EDGES_MAX;

    fused_sage_kernel<<<NBLOCKS, NTHREADS>>>(x, W1l, W1r, b1, W2l, W2r, b2, ei,
                                             n_nodes, n_edges, in_sizes[7],
                                             (float*)d_out);
}

// round 13
// speedup vs baseline: 1.5581x; 1.5581x over previous
#include <cuda_runtime.h>

#define IN_CH 64
#define HIDDEN 16
#define OUT_CH 8
#define N_NODES_MAX 50000
#define N_EDGES_MAX 800000
#define NTHREADS 256
#define NBLOCKS 740   // 148 SMs x 5 blocks, co-resident via __launch_bounds__(256,5)

// Scratch (allocation-free rule: __device__ globals). +1 dummy sink row.
// INVARIANT: g_deg and g_s1 are all-zero at kernel entry (zero-initialized at
// module load; each call re-zeroes exactly what it dirtied).
__device__ float g_deg[N_NODES_MAX + 1];
__device__ float g_p1[(N_NODES_MAX + 1) * HIDDEN];
__device__ float g_r1[N_NODES_MAX * HIDDEN];
__device__ float g_s1[(N_NODES_MAX + 1) * HIDDEN];
__device__ float g_p2[(N_NODES_MAX + 1) * OUT_CH];
__device__ float g_s2[(N_NODES_MAX + 1) * OUT_CH];
__device__ int   g_pedges[N_EDGES_MAX];      // packed (src<<16)|dst; invalid -> sink
__device__ int           g_bar_count;        // returns to 0 at kernel exit
__device__ volatile int  g_bar_gen;          // monotonic; ok across replays

// Vectorized global reduction (sm_90+): one L2 op for 4 floats.
__device__ __forceinline__ void red_add_v4(float* addr, float4 v) {
    asm volatile("red.global.add.v4.f32 [%0], {%1, %2, %3, %4};"
                 :: "l"(addr), "f"(v.x), "f"(v.y), "f"(v.z), "f"(v.w));
}

__device__ __forceinline__ float4 ldcg4(const float* p) {
    float4 v;
    asm volatile("ld.global.cg.v4.f32 {%0,%1,%2,%3}, [%4];"
                 : "=f"(v.x), "=f"(v.y), "=f"(v.z), "=f"(v.w) : "l"(p));
    return v;
}

// Software grid barrier (all NBLOCKS resident by launch_bounds + grid size).
__device__ __forceinline__ void grid_barrier() {
    __syncthreads();
    if (threadIdx.x == 0) {
        int gen = g_bar_gen;
        __threadfence();  // release (gpu scope)
        if (atomicAdd(&g_bar_count, 1) == NBLOCKS - 1) {
            g_bar_count = 0;
            __threadfence();
            g_bar_gen = gen + 1;
        } else {
            while (g_bar_gen == gen) __nanosleep(64);
        }
        __threadfence();  // acquire
    }
    __syncthreads();
}

__global__ void __launch_bounds__(NTHREADS, 5)
fused_sage_kernel(const float* __restrict__ x,
                  const float* __restrict__ W1l,
                  const float* __restrict__ W1r,
                  const float* __restrict__ b1,
                  const float* __restrict__ W2l,
                  const float* __restrict__ W2r,
                  const float* __restrict__ b2,
                  const int*   __restrict__ ei,
                  int n_nodes, int n_edges, int n_words,
                  float* __restrict__ out) {
    __shared__ float sW1l[HIDDEN * IN_CH];
    __shared__ float sW1r[HIDDEN * IN_CH];
    __shared__ float sb1[HIDDEN];
    __shared__ float sW2l[OUT_CH * HIDDEN];
    __shared__ float sW2r[OUT_CH * HIDDEN];
    __shared__ float sb2[OUT_CH];

    const int T = NBLOCKS * NTHREADS;
    const int t = blockIdx.x * NTHREADS + threadIdx.x;

    for (int i = threadIdx.x; i < HIDDEN * IN_CH; i += NTHREADS) {
        sW1l[i] = W1l[i];
        sW1r[i] = W1r[i];
    }
    for (int i = threadIdx.x; i < OUT_CH * HIDDEN; i += NTHREADS) {
        sW2l[i] = W2l[i];
        sW2r[i] = W2r[i];
    }
    if (threadIdx.x < HIDDEN) sb1[threadIdx.x] = b1[threadIdx.x];
    if (threadIdx.x < OUT_CH) sb2[threadIdx.x] = b2[threadIdx.x];

    // Parallel dtype detect: int64 little-endian indices in [0,50000) -> all
    // odd int32 words are 0; int32 -> random indices, never all zero over 256.
    int w = 2 * threadIdx.x + 1;
    int mine = (w < n_words) ? (ei[w] != 0) : 0;
    const int is64 = __syncthreads_or(mine) ? 0 : 1;

    // ---- Phase 1: gemm1 (8 thr/node, 2 ch each) || decode+pack edges -----
    for (int idx = t; idx < n_nodes * 8; idx += T) {
        int n = idx >> 3;
        int h0 = (idx & 7) * 2;
        float l0 = 0.f, l1 = 0.f;
        float r0 = sb1[h0], r1 = sb1[h0 + 1];
        const float4* xr = reinterpret_cast<const float4*>(x + (size_t)n * IN_CH);
        const float* wl0 = &sW1l[h0 * IN_CH];
        const float* wl1 = &sW1l[(h0 + 1) * IN_CH];
        const float* wr0 = &sW1r[h0 * IN_CH];
        const float* wr1 = &sW1r[(h0 + 1) * IN_CH];
#pragma unroll
        for (int c4 = 0; c4 < IN_CH / 4; c4++) {
            float4 v = xr[c4];
            int c = c4 * 4;
            l0 += v.x * wl0[c] + v.y * wl0[c + 1] + v.z * wl0[c + 2] + v.w * wl0[c + 3];
            l1 += v.x * wl1[c] + v.y * wl1[c + 1] + v.z * wl1[c + 2] + v.w * wl1[c + 3];
            r0 += v.x * wr0[c] + v.y * wr0[c + 1] + v.z * wr0[c + 2] + v.w * wr0[c + 3];
            r1 += v.x * wr1[c] + v.y * wr1[c + 1] + v.z * wr1[c + 2] + v.w * wr1[c + 3];
        }
        *reinterpret_cast<float2*>(&g_p1[n * HIDDEN + h0]) = make_float2(l0, l1);
        *reinterpret_cast<float2*>(&g_r1[n * HIDDEN + h0]) = make_float2(r0, r1);
    }
    // sink p-rows zero
    if (t < 4)
        *reinterpret_cast<float4*>(&g_p1[N_NODES_MAX * HIDDEN + t * 4]) =
            make_float4(0.f, 0.f, 0.f, 0.f);
    if (t >= 4 && t < 6)
        *reinterpret_cast<float4*>(&g_p2[N_NODES_MAX * OUT_CH + (t - 4) * 4]) =
            make_float4(0.f, 0.f, 0.f, 0.f);
    // decode + pack edges; count degree
    for (int e = t; e < n_edges; e += T) {
        int src, dst;
        if (is64) {
            const int2* p = reinterpret_cast<const int2*>(ei);
            src = p[e].x;
            dst = p[n_edges + e].x;
        } else {
            src = ei[e];
            dst = ei[n_edges + e];
        }
        bool ok = ((unsigned)src < (unsigned)n_nodes) & ((unsigned)dst < (unsigned)n_nodes);
        if (!ok) { src = N_NODES_MAX; dst = N_NODES_MAX; }
        g_pedges[e] = (src << 16) | dst;
        if (ok) atomicAdd(&g_deg[dst], 1.0f);
    }
    grid_barrier();

    // ---- Phase 2: scatter1, 4 thr/edge, packed ids, pipelined (U=4) ------
    {
        const int total = n_edges * 4;
        const int q4 = (t & 3) * 4;
        int idx = t;
        for (; idx + 3 * T < total; idx += 4 * T) {
            int pe[4];
#pragma unroll
            for (int u = 0; u < 4; u++) pe[u] = g_pedges[(idx + u * T) >> 2];
            float4 v[4];
#pragma unroll
            for (int u = 0; u < 4; u++)
                v[u] = *reinterpret_cast<const float4*>(
                    &g_p1[((unsigned)pe[u] >> 16) * HIDDEN + q4]);
#pragma unroll
            for (int u = 0; u < 4; u++)
                red_add_v4(&g_s1[(pe[u] & 0xFFFF) * HIDDEN + q4], v[u]);
        }
        for (; idx < total; idx += T) {
            int pe = g_pedges[idx >> 2];
            float4 v = *reinterpret_cast<const float4*>(
                &g_p1[((unsigned)pe >> 16) * HIDDEN + q4]);
            red_add_v4(&g_s1[(pe & 0xFFFF) * HIDDEN + q4], v);
        }
    }
    grid_barrier();

    // ---- Phase 3: layer2, 2 thr/node with pair shuffle-reduce ------------
    // Thread q in {0,1} owns h-channels [8q, 8q+8). Partial products over its
    // half are reduced across the lane pair; q writes output quarters.
    {
        const int total = n_nodes * 2;
        for (int base = 0; base < total; base += T) {
            int idx = base + t;
            bool valid = idx < total;
            int n = valid ? (idx >> 1) : (n_nodes - 1);
            int q = t & 1;                     // pair lanes: (even, odd)
            float dv;
            asm volatile("ld.global.cg.f32 %0, [%1];" : "=f"(dv) : "l"(&g_deg[n]));
            float deg_eff = fmaxf(dv, 1.0f);
            float inv_d = 1.0f / deg_eff;
            float h[8];
#pragma unroll
            for (int p = 0; p < 2; p++) {
                float4 sv = ldcg4(&g_s1[n * HIDDEN + q * 8 + p * 4]);
                float4 rv = *reinterpret_cast<const float4*>(
                    &g_r1[n * HIDDEN + q * 8 + p * 4]);
                h[p * 4 + 0] = fmaxf(sv.x * inv_d + rv.x, 0.0f);
                h[p * 4 + 1] = fmaxf(sv.y * inv_d + rv.y, 0.0f);
                h[p * 4 + 2] = fmaxf(sv.z * inv_d + rv.z, 0.0f);
                h[p * 4 + 3] = fmaxf(sv.w * inv_d + rv.w, 0.0f);
            }
            if (valid) {
                // restore all-zero invariant for next call (own half)
                *reinterpret_cast<float4*>(&g_s1[n * HIDDEN + q * 8]) =
                    make_float4(0.f, 0.f, 0.f, 0.f);
                *reinterpret_cast<float4*>(&g_s1[n * HIDDEN + q * 8 + 4]) =
                    make_float4(0.f, 0.f, 0.f, 0.f);
            }
            float accl[OUT_CH], accr[OUT_CH];
#pragma unroll
            for (int o = 0; o < OUT_CH; o++) {
                accl[o] = 0.0f;
                accr[o] = (q == 0) ? sb2[o] : 0.0f;  // bias counted once
            }
#pragma unroll
            for (int c = 0; c < 8; c++) {
                float v = h[c];
#pragma unroll
                for (int o = 0; o < OUT_CH; o++) {
                    accl[o] += v * sW2l[o * HIDDEN + q * 8 + c];
                    accr[o] += v * sW2r[o * HIDDEN + q * 8 + c];
                }
            }
#pragma unroll
            for (int o = 0; o < OUT_CH; o++) {
                accl[o] += __shfl_xor_sync(0xFFFFFFFFu, accl[o], 1);
                accr[o] += __shfl_xor_sync(0xFFFFFFFFu, accr[o], 1);
            }
            if (valid) {
                // q writes quarter q of p2 and of the s2 seed
                float4 pl = make_float4(accl[q * 4 + 0], accl[q * 4 + 1],
                                        accl[q * 4 + 2], accl[q * 4 + 3]);
                float4 sr = make_float4(accr[q * 4 + 0] * deg_eff,
                                        accr[q * 4 + 1] * deg_eff,
                                        accr[q * 4 + 2] * deg_eff,
                                        accr[q * 4 + 3] * deg_eff);
                *reinterpret_cast<float4*>(&g_p2[n * OUT_CH + q * 4]) = pl;
                *reinterpret_cast<float4*>(&g_s2[n * OUT_CH + q * 4]) = sr;
            }
        }
    }
    // s1 sink row: scatter1 dirtied it; re-zero for next call.
    if (t < 4)
        *reinterpret_cast<float4*>(&g_s1[N_NODES_MAX * HIDDEN + t * 4]) =
            make_float4(0.f, 0.f, 0.f, 0.f);
    grid_barrier();

    // ---- Phase 4: scatter2, 2 thr/edge, packed ids, pipelined (U=4) ------
    {
        const int total = n_edges * 2;
        const int q4 = (t & 1) * 4;
        int idx = t;
        for (; idx + 3 * T < total; idx += 4 * T) {
            int pe[4];
#pragma unroll
            for (int u = 0; u < 4; u++) pe[u] = g_pedges[(idx + u * T) >> 1];
            float4 v[4];
#pragma unroll
            for (int u = 0; u < 4; u++)
                v[u] = *reinterpret_cast<const float4*>(
                    &g_p2[((unsigned)pe[u] >> 16) * OUT_CH + q4]);
#pragma unroll
            for (int u = 0; u < 4; u++)
                red_add_v4(&g_s2[(pe[u] & 0xFFFF) * OUT_CH + q4], v[u]);
        }
        for (; idx < total; idx += T) {
            int pe = g_pedges[idx >> 1];
            float4 v = *reinterpret_cast<const float4*>(
                &g_p2[((unsigned)pe >> 16) * OUT_CH + q4]);
            red_add_v4(&g_s2[(pe & 0xFFFF) * OUT_CH + q4], v);
        }
    }
    grid_barrier();

    // ---- Phase 5: out = s2 * inv_deg ; re-zero deg behind us -------------
    for (int idx = t; idx < n_nodes * 2; idx += T) {
        int n = idx >> 1;
        int q = idx & 1;
        float dv;
        asm volatile("ld.global.cg.f32 %0, [%1];" : "=f"(dv) : "l"(&g_deg[n]));
        float inv_d = 1.0f / fmaxf(dv, 1.0f);
        float4 s = ldcg4(&g_s2[n * OUT_CH + q * 4]);
        float4 o;
        o.x = s.x * inv_d;
        o.y = s.y * inv_d;
        o.z = s.z * inv_d;
        o.w = s.w * inv_d;
        *reinterpret_cast<float4*>(&out[n * OUT_CH + q * 4]) = o;
        if (q == 0) g_deg[n] = 0.0f;   // same-warp pair: loads precede this store
    }
}

extern "C" void kernel_launch(void* const* d_in, const int* in_sizes, int n_in,
                              void* d_out, int out_size) {
    const float* x   = (const float*)d_in[0];
    const float* W1l = (const float*)d_in[1];
    const float* W1r = (const float*)d_in[2];
    const float* b1  = (const float*)d_in[3];
    const float* W2l = (const float*)d_in[4];
    const float* W2r = (const float*)d_in[5];
    const float* b2  = (const float*)d_in[6];
    const int*   ei  = (const int*)d_in[7];

    int n_nodes = in_sizes[0] / IN_CH;
    int n_edges = in_sizes[7] / 2;
    if (n_nodes > N_NODES_MAX) n_nodes = N_NODES_MAX;
    if (n_edges > N_EDGES_MAX) n_edges = N_EDGES_MAX;

    fused_sage_kernel<<<NBLOCKS, NTHREADS>>>(x, W1l, W1r, b1, W2l, W2r, b2, ei,
                                             n_nodes, n_edges, in_sizes[7],
                                             (float*)d_out);
}

// round 14
// speedup vs baseline: 2.1351x; 1.3703x over previous
#include <cuda_runtime.h>

#define IN_CH 64
#define HIDDEN 16
#define OUT_CH 8
#define N_NODES_MAX 50000
#define N_EDGES_MAX 800000
#define NTHREADS 256
#define NBLOCKS 592   // 148 SMs x 4 blocks, co-resident via __launch_bounds__(256,4)

// Scratch (allocation-free rule: __device__ globals). +1 dummy sink row.
__device__ float g_deg[N_NODES_MAX + 1];
__device__ float g_p1[(N_NODES_MAX + 1) * HIDDEN];
__device__ float g_r1[N_NODES_MAX * HIDDEN];
__device__ float g_s1[(N_NODES_MAX + 1) * HIDDEN];
__device__ float g_p2[(N_NODES_MAX + 1) * OUT_CH];
__device__ float g_s2[(N_NODES_MAX + 1) * OUT_CH];
__device__ int   g_pedges[N_EDGES_MAX];      // packed (src<<16)|dst; invalid -> sink
__device__ int           g_bar_count;        // returns to 0 at kernel exit
__device__ volatile int  g_bar_gen;          // monotonic; ok across replays

// Vectorized global reduction (sm_90+): one L2 op for 4 floats.
__device__ __forceinline__ void red_add_v4(float* addr, float4 v) {
    asm volatile("red.global.add.v4.f32 [%0], {%1, %2, %3, %4};"
                 :: "l"(addr), "f"(v.x), "f"(v.y), "f"(v.z), "f"(v.w)
                 : "memory");
}

__device__ __forceinline__ float4 ldcg4(const float* p) {
    float4 v;
    asm volatile("ld.global.cg.v4.f32 {%0,%1,%2,%3}, [%4];"
                 : "=f"(v.x), "=f"(v.y), "=f"(v.z), "=f"(v.w) : "l"(p));
    return v;
}

// Software grid barrier (all NBLOCKS resident by launch_bounds + grid size).
__device__ __forceinline__ void grid_barrier() {
    __syncthreads();
    if (threadIdx.x == 0) {
        int gen = g_bar_gen;
        __threadfence();  // release (gpu scope)
        if (atomicAdd(&g_bar_count, 1) == NBLOCKS - 1) {
            g_bar_count = 0;
            __threadfence();
            g_bar_gen = gen + 1;
        } else {
            while (g_bar_gen == gen) __nanosleep(64);
        }
        __threadfence();  // acquire
    }
    __syncthreads();
}

__global__ void __launch_bounds__(NTHREADS, 4)
fused_sage_kernel(const float* __restrict__ x,
                  const float* __restrict__ W1l,
                  const float* __restrict__ W1r,
                  const float* __restrict__ b1,
                  const float* __restrict__ W2l,
                  const float* __restrict__ W2r,
                  const float* __restrict__ b2,
                  const int*   __restrict__ ei,
                  int n_nodes, int n_edges, int n_words,
                  float* __restrict__ out) {
    __shared__ float sW1l[HIDDEN * IN_CH];
    __shared__ float sW1r[HIDDEN * IN_CH];
    __shared__ float sb1[HIDDEN];
    __shared__ float sW2l[OUT_CH * HIDDEN];
    __shared__ float sW2r[OUT_CH * HIDDEN];
    __shared__ float sb2[OUT_CH];

    const int T = NBLOCKS * NTHREADS;
    const int t = blockIdx.x * NTHREADS + threadIdx.x;

    for (int i = threadIdx.x; i < HIDDEN * IN_CH; i += NTHREADS) {
        sW1l[i] = W1l[i];
        sW1r[i] = W1r[i];
    }
    for (int i = threadIdx.x; i < OUT_CH * HIDDEN; i += NTHREADS) {
        sW2l[i] = W2l[i];
        sW2r[i] = W2r[i];
    }
    if (threadIdx.x < HIDDEN) sb1[threadIdx.x] = b1[threadIdx.x];
    if (threadIdx.x < OUT_CH) sb2[threadIdx.x] = b2[threadIdx.x];

    // Parallel dtype detect: int64 little-endian indices in [0,50000) -> all
    // odd int32 words are 0; int32 -> random indices, never all zero over 256.
    int w = 2 * threadIdx.x + 1;
    int mine = (w < n_words) ? (ei[w] != 0) : 0;
    const int is64 = __syncthreads_or(mine) ? 0 : 1;

    // ---- Phase 0: zero accumulators (deg incl. sink, s1, s2 sink row) ----
    for (int i = t; i < n_nodes + 1; i += T) g_deg[i] = 0.0f;
    for (int i = t; i < (n_nodes + 1) * HIDDEN; i += T) g_s1[i] = 0.0f;
    if (t < OUT_CH) g_s2[N_NODES_MAX * OUT_CH + t] = 0.0f;
    grid_barrier();

    // ---- Phase 1: gemm1 -> p1, r1  ||  decode+pack edges + degree count --
    for (int idx = t; idx < n_nodes * 4; idx += T) {
        int n = idx >> 2;
        int q = idx & 3;
        int h0 = q * 4;
        float accl[4], accr[4];
#pragma unroll
        for (int j = 0; j < 4; j++) { accl[j] = 0.0f; accr[j] = sb1[h0 + j]; }
        const float4* xr = reinterpret_cast<const float4*>(x + (size_t)n * IN_CH);
#pragma unroll
        for (int c4 = 0; c4 < IN_CH / 4; c4++) {
            float4 v = xr[c4];
#pragma unroll
            for (int j = 0; j < 4; j++) {
                const float* wl = &sW1l[(h0 + j) * IN_CH + c4 * 4];
                const float* wr = &sW1r[(h0 + j) * IN_CH + c4 * 4];
                accl[j] += v.x * wl[0] + v.y * wl[1] + v.z * wl[2] + v.w * wl[3];
                accr[j] += v.x * wr[0] + v.y * wr[1] + v.z * wr[2] + v.w * wr[3];
            }
        }
        *reinterpret_cast<float4*>(&g_p1[n * HIDDEN + h0]) =
            make_float4(accl[0], accl[1], accl[2], accl[3]);
        *reinterpret_cast<float4*>(&g_r1[n * HIDDEN + h0]) =
            make_float4(accr[0], accr[1], accr[2], accr[3]);
    }
    // zero the dummy sink p-rows
    if (t < 4)
        *reinterpret_cast<float4*>(&g_p1[N_NODES_MAX * HIDDEN + t * 4]) =
            make_float4(0.f, 0.f, 0.f, 0.f);
    if (t >= 4 && t < 6)
        *reinterpret_cast<float4*>(&g_p2[N_NODES_MAX * OUT_CH + (t - 4) * 4]) =
            make_float4(0.f, 0.f, 0.f, 0.f);
    // decode + pack edges (independent of gemm1 above)
    for (int e = t; e < n_edges; e += T) {
        int src, dst;
        if (is64) {
            const int2* p = reinterpret_cast<const int2*>(ei);
            src = p[e].x;
            dst = p[n_edges + e].x;
        } else {
            src = ei[e];
            dst = ei[n_edges + e];
        }
        bool ok = ((unsigned)src < (unsigned)n_nodes) & ((unsigned)dst < (unsigned)n_nodes);
        if (!ok) { src = N_NODES_MAX; dst = N_NODES_MAX; }
        g_pedges[e] = (src << 16) | dst;
        if (ok) atomicAdd(&g_deg[dst], 1.0f);
    }
    grid_barrier();

    // ---- Phase 2: scatter1, 4 thr/edge, packed ids, pipelined (U=4) ------
    {
        const int total = n_edges * 4;
        const int q4 = (t & 3) * 4;            // channel offset, invariant
        int idx = t;
        for (; idx + 3 * T < total; idx += 4 * T) {
            int pe[4];
#pragma unroll
            for (int u = 0; u < 4; u++) pe[u] = g_pedges[(idx + u * T) >> 2];
            float4 v[4];
#pragma unroll
            for (int u = 0; u < 4; u++)
                v[u] = *reinterpret_cast<const float4*>(
                    &g_p1[((unsigned)pe[u] >> 16) * HIDDEN + q4]);
#pragma unroll
            for (int u = 0; u < 4; u++)
                red_add_v4(&g_s1[(pe[u] & 0xFFFF) * HIDDEN + q4], v[u]);
        }
        for (; idx < total; idx += T) {
            int pe = g_pedges[idx >> 2];
            float4 v = *reinterpret_cast<const float4*>(
                &g_p1[((unsigned)pe >> 16) * HIDDEN + q4]);
            red_add_v4(&g_s1[(pe & 0xFFFF) * HIDDEN + q4], v);
        }
    }
    grid_barrier();

    // ---- Phase 3: layer2: h=relu(s1/deg + r1); p2 = h@W2l^T;
    //      s2 seeded with (h@W2r^T + b2) * deg_eff so phase 5 is a pure scale.
    for (int n = t; n < n_nodes; n += T) {
        float dv;
        asm volatile("ld.global.cg.f32 %0, [%1];" : "=f"(dv) : "l"(&g_deg[n]));
        float deg_eff = fmaxf(dv, 1.0f);
        float inv_d = 1.0f / deg_eff;
        float h[HIDDEN];
#pragma unroll
        for (int q = 0; q < HIDDEN / 4; q++) {
            float4 sv = ldcg4(&g_s1[n * HIDDEN + q * 4]);
            float4 rv = *reinterpret_cast<const float4*>(&g_r1[n * HIDDEN + q * 4]);
            h[q * 4 + 0] = fmaxf(sv.x * inv_d + rv.x, 0.0f);
            h[q * 4 + 1] = fmaxf(sv.y * inv_d + rv.y, 0.0f);
            h[q * 4 + 2] = fmaxf(sv.z * inv_d + rv.z, 0.0f);
            h[q * 4 + 3] = fmaxf(sv.w * inv_d + rv.w, 0.0f);
        }
        float accl[OUT_CH], accr[OUT_CH];
#pragma unroll
        for (int o = 0; o < OUT_CH; o++) { accl[o] = 0.0f; accr[o] = sb2[o]; }
#pragma unroll
        for (int c = 0; c < HIDDEN; c++) {
            float v = h[c];
#pragma unroll
            for (int o = 0; o < OUT_CH; o++) {
                accl[o] += v * sW2l[o * HIDDEN + c];
                accr[o] += v * sW2r[o * HIDDEN + c];
            }
        }
        float4* p2o = reinterpret_cast<float4*>(&g_p2[n * OUT_CH]);
        float4* s2o = reinterpret_cast<float4*>(&g_s2[n * OUT_CH]);
        p2o[0] = make_float4(accl[0], accl[1], accl[2], accl[3]);
        p2o[1] = make_float4(accl[4], accl[5], accl[6], accl[7]);
        s2o[0] = make_float4(accr[0] * deg_eff, accr[1] * deg_eff,
                             accr[2] * deg_eff, accr[3] * deg_eff);
        s2o[1] = make_float4(accr[4] * deg_eff, accr[5] * deg_eff,
                             accr[6] * deg_eff, accr[7] * deg_eff);
    }
    grid_barrier();

    // ---- Phase 4: scatter2, 2 thr/edge, packed ids, pipelined (U=4) ------
    {
        const int total = n_edges * 2;
        const int q4 = (t & 1) * 4;
        int idx = t;
        for (; idx + 3 * T < total; idx += 4 * T) {
            int pe[4];
#pragma unroll
            for (int u = 0; u < 4; u++) pe[u] = g_pedges[(idx + u * T) >> 1];
            float4 v[4];
#pragma unroll
            for (int u = 0; u < 4; u++)
                v[u] = *reinterpret_cast<const float4*>(
                    &g_p2[((unsigned)pe[u] >> 16) * OUT_CH + q4]);
#pragma unroll
            for (int u = 0; u < 4; u++)
                red_add_v4(&g_s2[(pe[u] & 0xFFFF) * OUT_CH + q4], v[u]);
        }
        for (; idx < total; idx += T) {
            int pe = g_pedges[idx >> 1];
            float4 v = *reinterpret_cast<const float4*>(
                &g_p2[((unsigned)pe >> 16) * OUT_CH + q4]);
            red_add_v4(&g_s2[(pe & 0xFFFF) * OUT_CH + q4], v);
        }
    }
    grid_barrier();

    // ---- Phase 5: out = s2 * inv_deg --------------------------------------
    for (int idx = t; idx < n_nodes * 2; idx += T) {
        int n = idx >> 1;
        int q = idx & 1;
        float dv;
        asm volatile("ld.global.cg.f32 %0, [%1];" : "=f"(dv) : "l"(&g_deg[n]));
        float inv_d = 1.0f / fmaxf(dv, 1.0f);
        float4 s = ldcg4(&g_s2[n * OUT_CH + q * 4]);
        float4 o;
        o.x = s.x * inv_d;
        o.y = s.y * inv_d;
        o.z = s.z * inv_d;
        o.w = s.w * inv_d;
        *reinterpret_cast<float4*>(&out[n * OUT_CH + q * 4]) = o;
    }
}

extern "C" void kernel_launch(void* const* d_in, const int* in_sizes, int n_in,
                              void* d_out, int out_size) {
    const float* x   = (const float*)d_in[0];
    const float* W1l = (const float*)d_in[1];
    const float* W1r = (const float*)d_in[2];
    const float* b1  = (const float*)d_in[3];
    const float* W2l = (const float*)d_in[4];
    const float* W2r = (const float*)d_in[5];
    const float* b2  = (const float*)d_in[6];
    const int*   ei  = (const int*)d_in[7];

    int n_nodes = in_sizes[0] / IN_CH;
    int n_edges = in_sizes[7] / 2;
    if (n_nodes > N_NODES_MAX) n_nodes = N_NODES_MAX;
    if (n_edges > N_EDGES_MAX) n_edges = N_EDGES_MAX;

    fused_sage_kernel<<<NBLOCKS, NTHREADS>>>(x, W1l, W1r, b1, W2l, W2r, b2, ei,
                                             n_nodes, n_edges, in_sizes[7],
                                             (float*)d_out);
}

// round 15
// speedup vs baseline: 2.2332x; 1.0460x over previous
#include <cuda_runtime.h>

#define IN_CH 64
#define HIDDEN 16
#define OUT_CH 8
#define N_NODES_MAX 50000
#define N_EDGES_MAX 800000
#define B 256

// Scratch (allocation-free rule: __device__ globals). +1 dummy sink row.
// INVARIANTS at kernel_launch entry (zero-init at load, restored each call):
//   g_deg[0..n_nodes)  == 0   (combine2 zeroes after last read)
//   g_s1 [0..n_nodes*H)== 0   (layer2 zeroes after last read)
// Sink rows of s1/s2 may accumulate garbage; they are never read.
__device__ float g_deg[N_NODES_MAX + 1];
__device__ float g_p1[(N_NODES_MAX + 1) * HIDDEN];
__device__ float g_r1[N_NODES_MAX * HIDDEN];
__device__ float g_s1[(N_NODES_MAX + 1) * HIDDEN];
__device__ float g_p2[(N_NODES_MAX + 1) * OUT_CH];
__device__ float g_s2[(N_NODES_MAX + 1) * OUT_CH];
__device__ int   g_pedges[N_EDGES_MAX];   // packed (src<<16)|dst; invalid -> sink

// Vectorized global reduction (sm_90+): one L2 op for 4 floats.
__device__ __forceinline__ void red_add_v4(float* addr, float4 v) {
    asm volatile("red.global.add.v4.f32 [%0], {%1, %2, %3, %4};"
                 :: "l"(addr), "f"(v.x), "f"(v.y), "f"(v.z), "f"(v.w)
                 : "memory");
}

// ---- K1: gemm1 (4 thr/node) + decode/pack edges + degree count -----------
__global__ void k1_gemm1_decode(const float* __restrict__ x,
                                const float* __restrict__ W1l,
                                const float* __restrict__ W1r,
                                const float* __restrict__ b1,
                                const int*   __restrict__ ei,
                                int n_nodes, int n_edges, int n_words) {
    __shared__ float sWl[HIDDEN * IN_CH];
    __shared__ float sWr[HIDDEN * IN_CH];
    __shared__ float sb[HIDDEN];
    for (int i = threadIdx.x; i < HIDDEN * IN_CH; i += B) {
        sWl[i] = W1l[i];
        sWr[i] = W1r[i];
    }
    if (threadIdx.x < HIDDEN) sb[threadIdx.x] = b1[threadIdx.x];

    // Parallel dtype detect: int64 little-endian indices in [0,50000) -> all
    // odd int32 words are 0; int32 -> random indices, never all zero over 256.
    int w = 2 * threadIdx.x + 1;
    int mine = (w < n_words) ? (ei[w] != 0) : 0;
    const int is64 = __syncthreads_or(mine) ? 0 : 1;

    const int T = gridDim.x * B;
    const int t = blockIdx.x * B + threadIdx.x;

    for (int idx = t; idx < n_nodes * 4; idx += T) {
        int n = idx >> 2;
        int q = idx & 3;
        int h0 = q * 4;
        float accl[4], accr[4];
#pragma unroll
        for (int j = 0; j < 4; j++) { accl[j] = 0.0f; accr[j] = sb[h0 + j]; }
        const float4* xr = reinterpret_cast<const float4*>(x + (size_t)n * IN_CH);
#pragma unroll
        for (int c4 = 0; c4 < IN_CH / 4; c4++) {
            float4 v = xr[c4];
#pragma unroll
            for (int j = 0; j < 4; j++) {
                const float* wl = &sWl[(h0 + j) * IN_CH + c4 * 4];
                const float* wr = &sWr[(h0 + j) * IN_CH + c4 * 4];
                accl[j] += v.x * wl[0] + v.y * wl[1] + v.z * wl[2] + v.w * wl[3];
                accr[j] += v.x * wr[0] + v.y * wr[1] + v.z * wr[2] + v.w * wr[3];
            }
        }
        *reinterpret_cast<float4*>(&g_p1[n * HIDDEN + h0]) =
            make_float4(accl[0], accl[1], accl[2], accl[3]);
        *reinterpret_cast<float4*>(&g_r1[n * HIDDEN + h0]) =
            make_float4(accr[0], accr[1], accr[2], accr[3]);
    }
    // sink p-rows zero (once per call)
    if (t < 4)
        *reinterpret_cast<float4*>(&g_p1[N_NODES_MAX * HIDDEN + t * 4]) =
            make_float4(0.f, 0.f, 0.f, 0.f);
    if (t >= 4 && t < 6)
        *reinterpret_cast<float4*>(&g_p2[N_NODES_MAX * OUT_CH + (t - 4) * 4]) =
            make_float4(0.f, 0.f, 0.f, 0.f);
    // decode + pack edges; count degree (g_deg all-zero at entry by invariant)
    for (int e = t; e < n_edges; e += T) {
        int src, dst;
        if (is64) {
            const int2* p = reinterpret_cast<const int2*>(ei);
            src = p[e].x;
            dst = p[n_edges + e].x;
        } else {
            src = ei[e];
            dst = ei[n_edges + e];
        }
        bool ok = ((unsigned)src < (unsigned)n_nodes) & ((unsigned)dst < (unsigned)n_nodes);
        if (!ok) { src = N_NODES_MAX; dst = N_NODES_MAX; }
        g_pedges[e] = (src << 16) | dst;
        if (ok) atomicAdd(&g_deg[dst], 1.0f);
    }
}

// ---- K2: scatter1, 4 threads/edge (low-reg, max occupancy) ---------------
__global__ void k2_scatter1(int n_edges) {
    int idx = blockIdx.x * B + threadIdx.x;
    if (idx >= n_edges * 4) return;
    int pe = g_pedges[idx >> 2];               // broadcast within quad
    int q4 = (idx & 3) * 4;
    float4 v = *reinterpret_cast<const float4*>(
        &g_p1[((unsigned)pe >> 16) * HIDDEN + q4]);
    red_add_v4(&g_s1[(pe & 0xFFFF) * HIDDEN + q4], v);
}

// ---- K3: layer2: h=relu(s1/deg+r1); p2=h@W2l^T; s2 seeded; s1 re-zeroed --
__global__ void k3_layer2(const float* __restrict__ W2l,
                          const float* __restrict__ W2r,
                          const float* __restrict__ b2,
                          int n_nodes) {
    __shared__ float sWl[OUT_CH * HIDDEN];
    __shared__ float sWr[OUT_CH * HIDDEN];
    __shared__ float sb[OUT_CH];
    for (int i = threadIdx.x; i < OUT_CH * HIDDEN; i += B) {
        sWl[i] = W2l[i];
        sWr[i] = W2r[i];
    }
    if (threadIdx.x < OUT_CH) sb[threadIdx.x] = b2[threadIdx.x];
    __syncthreads();

    int n = blockIdx.x * B + threadIdx.x;
    if (n >= n_nodes) return;

    float deg_eff = fmaxf(g_deg[n], 1.0f);
    float inv_d = 1.0f / deg_eff;
    float h[HIDDEN];
#pragma unroll
    for (int q = 0; q < HIDDEN / 4; q++) {
        float4 sv = *reinterpret_cast<const float4*>(&g_s1[n * HIDDEN + q * 4]);
        float4 rv = *reinterpret_cast<const float4*>(&g_r1[n * HIDDEN + q * 4]);
        h[q * 4 + 0] = fmaxf(sv.x * inv_d + rv.x, 0.0f);
        h[q * 4 + 1] = fmaxf(sv.y * inv_d + rv.y, 0.0f);
        h[q * 4 + 2] = fmaxf(sv.z * inv_d + rv.z, 0.0f);
        h[q * 4 + 3] = fmaxf(sv.w * inv_d + rv.w, 0.0f);
        // restore all-zero invariant for the next call
        *reinterpret_cast<float4*>(&g_s1[n * HIDDEN + q * 4]) =
            make_float4(0.f, 0.f, 0.f, 0.f);
    }
    float accl[OUT_CH], accr[OUT_CH];
#pragma unroll
    for (int o = 0; o < OUT_CH; o++) { accl[o] = 0.0f; accr[o] = sb[o]; }
#pragma unroll
    for (int c = 0; c < HIDDEN; c++) {
        float v = h[c];
#pragma unroll
        for (int o = 0; o < OUT_CH; o++) {
            accl[o] += v * sWl[o * HIDDEN + c];
            accr[o] += v * sWr[o * HIDDEN + c];
        }
    }
    float4* p2o = reinterpret_cast<float4*>(&g_p2[n * OUT_CH]);
    float4* s2o = reinterpret_cast<float4*>(&g_s2[n * OUT_CH]);
    p2o[0] = make_float4(accl[0], accl[1], accl[2], accl[3]);
    p2o[1] = make_float4(accl[4], accl[5], accl[6], accl[7]);
    s2o[0] = make_float4(accr[0] * deg_eff, accr[1] * deg_eff,
                         accr[2] * deg_eff, accr[3] * deg_eff);
    s2o[1] = make_float4(accr[4] * deg_eff, accr[5] * deg_eff,
                         accr[6] * deg_eff, accr[7] * deg_eff);
}

// ---- K4: scatter2, 2 threads/edge (low-reg, max occupancy) ---------------
__global__ void k4_scatter2(int n_edges) {
    int idx = blockIdx.x * B + threadIdx.x;
    if (idx >= n_edges * 2) return;
    int pe = g_pedges[idx >> 1];               // broadcast within pair
    int q4 = (idx & 1) * 4;
    float4 v = *reinterpret_cast<const float4*>(
        &g_p2[((unsigned)pe >> 16) * OUT_CH + q4]);
    red_add_v4(&g_s2[(pe & 0xFFFF) * OUT_CH + q4], v);
}

// ---- K5: out = s2 * inv_deg ; restore deg invariant -----------------------
__global__ void k5_combine2(float* __restrict__ out, int n_nodes) {
    int idx = blockIdx.x * B + threadIdx.x;
    if (idx >= n_nodes * 2) return;
    int n = idx >> 1;
    int q = idx & 1;
    float inv_d = 1.0f / fmaxf(g_deg[n], 1.0f);
    float4 s = *reinterpret_cast<const float4*>(&g_s2[n * OUT_CH + q * 4]);
    float4 o;
    o.x = s.x * inv_d;
    o.y = s.y * inv_d;
    o.z = s.z * inv_d;
    o.w = s.w * inv_d;
    *reinterpret_cast<float4*>(&out[n * OUT_CH + q * 4]) = o;
    if (q == 0) g_deg[n] = 0.0f;   // pair lanes read before this same-warp store
}

extern "C" void kernel_launch(void* const* d_in, const int* in_sizes, int n_in,
                              void* d_out, int out_size) {
    const float* x   = (const float*)d_in[0];
    const float* W1l = (const float*)d_in[1];
    const float* W1r = (const float*)d_in[2];
    const float* b1  = (const float*)d_in[3];
    const float* W2l = (const float*)d_in[4];
    const float* W2r = (const float*)d_in[5];
    const float* b2  = (const float*)d_in[6];
    const int*   ei  = (const int*)d_in[7];

    int n_nodes = in_sizes[0] / IN_CH;
    int n_edges = in_sizes[7] / 2;
    if (n_nodes > N_NODES_MAX) n_nodes = N_NODES_MAX;
    if (n_edges > N_EDGES_MAX) n_edges = N_EDGES_MAX;

    int g1 = (n_edges + B - 1) / B;            // covers decode; gemm grid-strides
    k1_gemm1_decode<<<g1, B>>>(x, W1l, W1r, b1, ei, n_nodes, n_edges, in_sizes[7]);
    k2_scatter1<<<(n_edges * 4 + B - 1) / B, B>>>(n_edges);
    k3_layer2<<<(n_nodes + B - 1) / B, B>>>(W2l, W2r, b2, n_nodes);
    k4_scatter2<<<(n_edges * 2 + B - 1) / B, B>>>(n_edges);
    k5_combine2<<<(n_nodes * 2 + B - 1) / B, B>>>((float*)d_out, n_nodes);
}

// round 16
// speedup vs baseline: 2.2826x; 1.0221x over previous
#include <cuda_runtime.h>

#define IN_CH 64
#define HIDDEN 16
#define OUT_CH 8
#define N_NODES_MAX 50000
#define N_EDGES_MAX 800000
#define B 256

// Scratch (allocation-free rule: __device__ globals). +1 dummy sink row.
// INVARIANTS at kernel_launch entry (zero-init at load, restored each call):
//   g_deg[0..n_nodes)  == 0   (combine2 zeroes after last read)
//   g_s1 [0..n_nodes*H)== 0   (layer2 zeroes after last read)
// Sink rows of s1/s2 may accumulate garbage; they are never read.
__device__ float g_deg[N_NODES_MAX + 1];
__device__ float g_p1[(N_NODES_MAX + 1) * HIDDEN];
__device__ float g_r1[N_NODES_MAX * HIDDEN];
__device__ float g_s1[(N_NODES_MAX + 1) * HIDDEN];
__device__ float g_p2[(N_NODES_MAX + 1) * OUT_CH];
__device__ float g_s2[(N_NODES_MAX + 1) * OUT_CH];
__device__ int   g_pedges[N_EDGES_MAX];   // packed (src<<16)|dst; invalid -> sink

// Vectorized global reduction (sm_90+): one L2 op for 4 floats.
__device__ __forceinline__ void red_add_v4(float* addr, float4 v) {
    asm volatile("red.global.add.v4.f32 [%0], {%1, %2, %3, %4};"
                 :: "l"(addr), "f"(v.x), "f"(v.y), "f"(v.z), "f"(v.w)
                 : "memory");
}

// ---- K1: gemm1 (4 thr/node) + decode/pack edges + degree count -----------
__global__ void k1_gemm1_decode(const float* __restrict__ x,
                                const float* __restrict__ W1l,
                                const float* __restrict__ W1r,
                                const float* __restrict__ b1,
                                const int*   __restrict__ ei,
                                int n_nodes, int n_edges, int n_words) {
    __shared__ float sWl[HIDDEN * IN_CH];
    __shared__ float sWr[HIDDEN * IN_CH];
    __shared__ float sb[HIDDEN];
    for (int i = threadIdx.x; i < HIDDEN * IN_CH; i += B) {
        sWl[i] = W1l[i];
        sWr[i] = W1r[i];
    }
    if (threadIdx.x < HIDDEN) sb[threadIdx.x] = b1[threadIdx.x];

    // Parallel dtype detect: int64 little-endian indices in [0,50000) -> all
    // odd int32 words are 0; int32 -> random indices, never all zero over 256.
    int w = 2 * threadIdx.x + 1;
    int mine = (w < n_words) ? (ei[w] != 0) : 0;
    const int is64 = __syncthreads_or(mine) ? 0 : 1;

    const int T = gridDim.x * B;
    const int t = blockIdx.x * B + threadIdx.x;

    for (int idx = t; idx < n_nodes * 4; idx += T) {
        int n = idx >> 2;
        int q = idx & 3;
        int h0 = q * 4;
        float accl[4], accr[4];
#pragma unroll
        for (int j = 0; j < 4; j++) { accl[j] = 0.0f; accr[j] = sb[h0 + j]; }
        const float4* xr = reinterpret_cast<const float4*>(x + (size_t)n * IN_CH);
#pragma unroll
        for (int c4 = 0; c4 < IN_CH / 4; c4++) {
            float4 v = xr[c4];
#pragma unroll
            for (int j = 0; j < 4; j++) {
                const float* wl = &sWl[(h0 + j) * IN_CH + c4 * 4];
                const float* wr = &sWr[(h0 + j) * IN_CH + c4 * 4];
                accl[j] += v.x * wl[0] + v.y * wl[1] + v.z * wl[2] + v.w * wl[3];
                accr[j] += v.x * wr[0] + v.y * wr[1] + v.z * wr[2] + v.w * wr[3];
            }
        }
        *reinterpret_cast<float4*>(&g_p1[n * HIDDEN + h0]) =
            make_float4(accl[0], accl[1], accl[2], accl[3]);
        *reinterpret_cast<float4*>(&g_r1[n * HIDDEN + h0]) =
            make_float4(accr[0], accr[1], accr[2], accr[3]);
    }
    // sink p-rows zero (once per call)
    if (t < 4)
        *reinterpret_cast<float4*>(&g_p1[N_NODES_MAX * HIDDEN + t * 4]) =
            make_float4(0.f, 0.f, 0.f, 0.f);
    if (t >= 4 && t < 6)
        *reinterpret_cast<float4*>(&g_p2[N_NODES_MAX * OUT_CH + (t - 4) * 4]) =
            make_float4(0.f, 0.f, 0.f, 0.f);
    // decode + pack edges; count degree (g_deg all-zero at entry by invariant)
    for (int e = t; e < n_edges; e += T) {
        int src, dst;
        if (is64) {
            const int2* p = reinterpret_cast<const int2*>(ei);
            src = p[e].x;
            dst = p[n_edges + e].x;
        } else {
            src = ei[e];
            dst = ei[n_edges + e];
        }
        bool ok = ((unsigned)src < (unsigned)n_nodes) & ((unsigned)dst < (unsigned)n_nodes);
        if (!ok) { src = N_NODES_MAX; dst = N_NODES_MAX; }
        g_pedges[e] = (src << 16) | dst;
        if (ok) atomicAdd(&g_deg[dst], 1.0f);
    }
}

// ---- K2: scatter1, 4 threads/edge (low-reg, max occupancy) ---------------
__global__ void k2_scatter1(int n_edges) {
    int idx = blockIdx.x * B + threadIdx.x;
    int q4 = (idx & 3) * 4;
    cudaGridDependencySynchronize();   // wait for k1's p1/pedges/deg
    if (idx >= n_edges * 4) return;
    int pe = g_pedges[idx >> 2];               // broadcast within quad
    float4 v = *reinterpret_cast<const float4*>(
        &g_p1[((unsigned)pe >> 16) * HIDDEN + q4]);
    red_add_v4(&g_s1[(pe & 0xFFFF) * HIDDEN + q4], v);
}

// ---- K3: layer2: h=relu(s1/deg+r1); p2=h@W2l^T; s2 seeded; s1 re-zeroed --
__global__ void k3_layer2(const float* __restrict__ W2l,
                          const float* __restrict__ W2r,
                          const float* __restrict__ b2,
                          int n_nodes) {
    __shared__ float sWl[OUT_CH * HIDDEN];
    __shared__ float sWr[OUT_CH * HIDDEN];
    __shared__ float sb[OUT_CH];
    // Prologue independent of k2: overlaps with scatter1 under PDL.
    for (int i = threadIdx.x; i < OUT_CH * HIDDEN; i += B) {
        sWl[i] = W2l[i];
        sWr[i] = W2r[i];
    }
    if (threadIdx.x < OUT_CH) sb[threadIdx.x] = b2[threadIdx.x];
    __syncthreads();
    cudaGridDependencySynchronize();   // wait for k2's s1 REDs

    int n = blockIdx.x * B + threadIdx.x;
    if (n >= n_nodes) return;

    float deg_eff = fmaxf(g_deg[n], 1.0f);
    float inv_d = 1.0f / deg_eff;
    float h[HIDDEN];
#pragma unroll
    for (int q = 0; q < HIDDEN / 4; q++) {
        float4 sv = *reinterpret_cast<const float4*>(&g_s1[n * HIDDEN + q * 4]);
        float4 rv = *reinterpret_cast<const float4*>(&g_r1[n * HIDDEN + q * 4]);
        h[q * 4 + 0] = fmaxf(sv.x * inv_d + rv.x, 0.0f);
        h[q * 4 + 1] = fmaxf(sv.y * inv_d + rv.y, 0.0f);
        h[q * 4 + 2] = fmaxf(sv.z * inv_d + rv.z, 0.0f);
        h[q * 4 + 3] = fmaxf(sv.w * inv_d + rv.w, 0.0f);
        // restore all-zero invariant for the next call
        *reinterpret_cast<float4*>(&g_s1[n * HIDDEN + q * 4]) =
            make_float4(0.f, 0.f, 0.f, 0.f);
    }
    float accl[OUT_CH], accr[OUT_CH];
#pragma unroll
    for (int o = 0; o < OUT_CH; o++) { accl[o] = 0.0f; accr[o] = sb[o]; }
#pragma unroll
    for (int c = 0; c < HIDDEN; c++) {
        float v = h[c];
#pragma unroll
        for (int o = 0; o < OUT_CH; o++) {
            accl[o] += v * sWl[o * HIDDEN + c];
            accr[o] += v * sWr[o * HIDDEN + c];
        }
    }
    float4* p2o = reinterpret_cast<float4*>(&g_p2[n * OUT_CH]);
    float4* s2o = reinterpret_cast<float4*>(&g_s2[n * OUT_CH]);
    p2o[0] = make_float4(accl[0], accl[1], accl[2], accl[3]);
    p2o[1] = make_float4(accl[4], accl[5], accl[6], accl[7]);
    s2o[0] = make_float4(accr[0] * deg_eff, accr[1] * deg_eff,
                         accr[2] * deg_eff, accr[3] * deg_eff);
    s2o[1] = make_float4(accr[4] * deg_eff, accr[5] * deg_eff,
                         accr[6] * deg_eff, accr[7] * deg_eff);
}

// ---- K4: scatter2, 2 threads/edge (low-reg, max occupancy) ---------------
__global__ void k4_scatter2(int n_edges) {
    int idx = blockIdx.x * B + threadIdx.x;
    int q4 = (idx & 1) * 4;
    cudaGridDependencySynchronize();   // wait for k3's p2/s2 seed
    if (idx >= n_edges * 2) return;
    int pe = g_pedges[idx >> 1];               // broadcast within pair
    float4 v = *reinterpret_cast<const float4*>(
        &g_p2[((unsigned)pe >> 16) * OUT_CH + q4]);
    red_add_v4(&g_s2[(pe & 0xFFFF) * OUT_CH + q4], v);
}

// ---- K5: out = s2 * inv_deg ; restore deg invariant -----------------------
__global__ void k5_combine2(float* __restrict__ out, int n_nodes) {
    int idx = blockIdx.x * B + threadIdx.x;
    int n = idx >> 1;
    int q = idx & 1;
    cudaGridDependencySynchronize();   // wait for k4's s2 REDs
    if (idx >= n_nodes * 2) return;
    float inv_d = 1.0f / fmaxf(g_deg[n], 1.0f);
    float4 s = *reinterpret_cast<const float4*>(&g_s2[n * OUT_CH + q * 4]);
    float4 o;
    o.x = s.x * inv_d;
    o.y = s.y * inv_d;
    o.z = s.z * inv_d;
    o.w = s.w * inv_d;
    *reinterpret_cast<float4*>(&out[n * OUT_CH + q * 4]) = o;
    if (q == 0) g_deg[n] = 0.0f;   // pair lanes read before this same-warp store
}

extern "C" void kernel_launch(void* const* d_in, const int* in_sizes, int n_in,
                              void* d_out, int out_size) {
    const float* x   = (const float*)d_in[0];
    const float* W1l = (const float*)d_in[1];
    const float* W1r = (const float*)d_in[2];
    const float* b1  = (const float*)d_in[3];
    const float* W2l = (const float*)d_in[4];
    const float* W2r = (const float*)d_in[5];
    const float* b2  = (const float*)d_in[6];
    const int*   ei  = (const int*)d_in[7];

    int n_nodes = in_sizes[0] / IN_CH;
    int n_edges = in_sizes[7] / 2;
    if (n_nodes > N_NODES_MAX) n_nodes = N_NODES_MAX;
    if (n_edges > N_EDGES_MAX) n_edges = N_EDGES_MAX;

    // K1: plain launch (first node; consumes prior call's restored invariants).
    int g1 = (n_edges + B - 1) / B;            // covers decode; gemm grid-strides
    k1_gemm1_decode<<<g1, B>>>(x, W1l, W1r, b1, ei, n_nodes, n_edges, in_sizes[7]);

    // K2..K5: programmatic dependent launches — successor blocks spin up and
    // run their independent prologue while the predecessor finishes.
    cudaLaunchAttribute attr[1];
    attr[0].id = cudaLaunchAttributeProgrammaticStreamSerialization;
    attr[0].val.programmaticStreamSerializationAllowed = 1;

    cudaLaunchConfig_t cfg = {};
    cfg.blockDim = dim3(B, 1, 1);
    cfg.attrs = attr;
    cfg.numAttrs = 1;
    cfg.stream = 0;

    cfg.gridDim = dim3((unsigned)((n_edges * 4 + B - 1) / B), 1, 1);
    cudaLaunchKernelEx(&cfg, k2_scatter1, n_edges);

    cfg.gridDim = dim3((unsigned)((n_nodes + B - 1) / B), 1, 1);
    cudaLaunchKernelEx(&cfg, k3_layer2, W2l, W2r, b2, n_nodes);

    cfg.gridDim = dim3((unsigned)((n_edges * 2 + B - 1) / B), 1, 1);
    cudaLaunchKernelEx(&cfg, k4_scatter2, n_edges);

    cfg.gridDim = dim3((unsigned)((n_nodes * 2 + B - 1) / B), 1, 1);
    cudaLaunchKernelEx(&cfg, k5_combine2, (float*)d_out, n_nodes);
}

// round 17
// speedup vs baseline: 2.3508x; 1.0299x over previous
#include <cuda_runtime.h>

#define IN_CH 64
#define HIDDEN 16
#define OUT_CH 8
#define N_NODES_MAX 50000
#define N_EDGES_MAX 800000
#define B 256

// Scratch (allocation-free rule: __device__ globals). +1 dummy sink row.
// INVARIANTS at kernel_launch entry (zero-init at load, restored each call):
//   g_deg[0..n_nodes)  == 0   (k3 zeroes after last read)
//   g_s1 [0..n_nodes*H)== 0   (k3 zeroes after last read)
// Sink rows of s1 accumulate only zeros (p1 sink row is zeroed); g_invd sink
// stays 0.0 forever (never written), so sink REDs in k4 add 0 to g_dummy.
__device__ float g_deg[N_NODES_MAX + 1];
__device__ float g_invd[N_NODES_MAX + 1];
__device__ float g_p1[(N_NODES_MAX + 1) * HIDDEN];
__device__ float g_r1[N_NODES_MAX * HIDDEN];
__device__ float g_s1[(N_NODES_MAX + 1) * HIDDEN];
__device__ float g_p2[(N_NODES_MAX + 1) * OUT_CH];
__device__ float g_dummy[OUT_CH];         // RED sink for invalid edges
__device__ int   g_pedges[N_EDGES_MAX];   // packed (src<<16)|dst; invalid -> sink

// Vectorized global reduction (sm_90+): one L2 op for 4 floats.
__device__ __forceinline__ void red_add_v4(float* addr, float4 v) {
    asm volatile("red.global.add.v4.f32 [%0], {%1, %2, %3, %4};"
                 :: "l"(addr), "f"(v.x), "f"(v.y), "f"(v.z), "f"(v.w)
                 : "memory");
}

// ---- K1: gemm1 (4 thr/node) + decode/pack edges + degree count -----------
__global__ void k1_gemm1_decode(const float* __restrict__ x,
                                const float* __restrict__ W1l,
                                const float* __restrict__ W1r,
                                const float* __restrict__ b1,
                                const int*   __restrict__ ei,
                                int n_nodes, int n_edges, int n_words) {
    __shared__ float sWl[HIDDEN * IN_CH];
    __shared__ float sWr[HIDDEN * IN_CH];
    __shared__ float sb[HIDDEN];
    for (int i = threadIdx.x; i < HIDDEN * IN_CH; i += B) {
        sWl[i] = W1l[i];
        sWr[i] = W1r[i];
    }
    if (threadIdx.x < HIDDEN) sb[threadIdx.x] = b1[threadIdx.x];

    // Parallel dtype detect: int64 little-endian indices in [0,50000) -> all
    // odd int32 words are 0; int32 -> random indices, never all zero over 256.
    int w = 2 * threadIdx.x + 1;
    int mine = (w < n_words) ? (ei[w] != 0) : 0;
    const int is64 = __syncthreads_or(mine) ? 0 : 1;

    const int T = gridDim.x * B;
    const int t = blockIdx.x * B + threadIdx.x;

    for (int idx = t; idx < n_nodes * 4; idx += T) {
        int n = idx >> 2;
        int q = idx & 3;
        int h0 = q * 4;
        float accl[4], accr[4];
#pragma unroll
        for (int j = 0; j < 4; j++) { accl[j] = 0.0f; accr[j] = sb[h0 + j]; }
        const float4* xr = reinterpret_cast<const float4*>(x + (size_t)n * IN_CH);
#pragma unroll
        for (int c4 = 0; c4 < IN_CH / 4; c4++) {
            float4 v = xr[c4];
#pragma unroll
            for (int j = 0; j < 4; j++) {
                const float* wl = &sWl[(h0 + j) * IN_CH + c4 * 4];
                const float* wr = &sWr[(h0 + j) * IN_CH + c4 * 4];
                accl[j] += v.x * wl[0] + v.y * wl[1] + v.z * wl[2] + v.w * wl[3];
                accr[j] += v.x * wr[0] + v.y * wr[1] + v.z * wr[2] + v.w * wr[3];
            }
        }
        *reinterpret_cast<float4*>(&g_p1[n * HIDDEN + h0]) =
            make_float4(accl[0], accl[1], accl[2], accl[3]);
        *reinterpret_cast<float4*>(&g_r1[n * HIDDEN + h0]) =
            make_float4(accr[0], accr[1], accr[2], accr[3]);
    }
    // sink p-rows zero (once per call)
    if (t < 4)
        *reinterpret_cast<float4*>(&g_p1[N_NODES_MAX * HIDDEN + t * 4]) =
            make_float4(0.f, 0.f, 0.f, 0.f);
    if (t >= 4 && t < 6)
        *reinterpret_cast<float4*>(&g_p2[N_NODES_MAX * OUT_CH + (t - 4) * 4]) =
            make_float4(0.f, 0.f, 0.f, 0.f);
    // decode + pack edges; count degree (g_deg all-zero at entry by invariant)
    for (int e = t; e < n_edges; e += T) {
        int src, dst;
        if (is64) {
            const int2* p = reinterpret_cast<const int2*>(ei);
            src = p[e].x;
            dst = p[n_edges + e].x;
        } else {
            src = ei[e];
            dst = ei[n_edges + e];
        }
        bool ok = ((unsigned)src < (unsigned)n_nodes) & ((unsigned)dst < (unsigned)n_nodes);
        if (!ok) { src = N_NODES_MAX; dst = N_NODES_MAX; }
        g_pedges[e] = (src << 16) | dst;
        if (ok) atomicAdd(&g_deg[dst], 1.0f);
    }
}

// ---- K2: scatter1, 4 threads/edge (low-reg, max occupancy) ---------------
__global__ void k2_scatter1(int n_edges) {
    int idx = blockIdx.x * B + threadIdx.x;
    int q4 = (idx & 3) * 4;
    cudaGridDependencySynchronize();   // wait for k1's p1/pedges/deg
    if (idx >= n_edges * 4) return;
    int pe = g_pedges[idx >> 2];               // broadcast within quad
    float4 v = *reinterpret_cast<const float4*>(
        &g_p1[((unsigned)pe >> 16) * HIDDEN + q4]);
    red_add_v4(&g_s1[(pe & 0xFFFF) * HIDDEN + q4], v);
}

// ---- K3: layer2: h=relu(s1/deg+r1); p2=h@W2l^T; out seeded with r2;
//      g_invd written; s1 and deg invariants restored ----------------------
__global__ void k3_layer2(const float* __restrict__ W2l,
                          const float* __restrict__ W2r,
                          const float* __restrict__ b2,
                          int n_nodes, float* __restrict__ out) {
    __shared__ float sWl[OUT_CH * HIDDEN];
    __shared__ float sWr[OUT_CH * HIDDEN];
    __shared__ float sb[OUT_CH];
    // Prologue independent of k2: overlaps with scatter1 under PDL.
    for (int i = threadIdx.x; i < OUT_CH * HIDDEN; i += B) {
        sWl[i] = W2l[i];
        sWr[i] = W2r[i];
    }
    if (threadIdx.x < OUT_CH) sb[threadIdx.x] = b2[threadIdx.x];
    __syncthreads();
    cudaGridDependencySynchronize();   // wait for k2's s1 REDs

    int n = blockIdx.x * B + threadIdx.x;
    if (n >= n_nodes) return;

    float deg_eff = fmaxf(g_deg[n], 1.0f);
    float inv_d = 1.0f / deg_eff;
    g_invd[n] = inv_d;                 // for k4's scale-at-RED
    g_deg[n] = 0.0f;                   // restore invariant (after last read)
    float h[HIDDEN];
#pragma unroll
    for (int q = 0; q < HIDDEN / 4; q++) {
        float4 sv = *reinterpret_cast<const float4*>(&g_s1[n * HIDDEN + q * 4]);
        float4 rv = *reinterpret_cast<const float4*>(&g_r1[n * HIDDEN + q * 4]);
        h[q * 4 + 0] = fmaxf(sv.x * inv_d + rv.x, 0.0f);
        h[q * 4 + 1] = fmaxf(sv.y * inv_d + rv.y, 0.0f);
        h[q * 4 + 2] = fmaxf(sv.z * inv_d + rv.z, 0.0f);
        h[q * 4 + 3] = fmaxf(sv.w * inv_d + rv.w, 0.0f);
        // restore all-zero invariant for the next call
        *reinterpret_cast<float4*>(&g_s1[n * HIDDEN + q * 4]) =
            make_float4(0.f, 0.f, 0.f, 0.f);
    }
    float accl[OUT_CH], accr[OUT_CH];
#pragma unroll
    for (int o = 0; o < OUT_CH; o++) { accl[o] = 0.0f; accr[o] = sb[o]; }
#pragma unroll
    for (int c = 0; c < HIDDEN; c++) {
        float v = h[c];
#pragma unroll
        for (int o = 0; o < OUT_CH; o++) {
            accl[o] += v * sWl[o * HIDDEN + c];
            accr[o] += v * sWr[o * HIDDEN + c];
        }
    }
    float4* p2o = reinterpret_cast<float4*>(&g_p2[n * OUT_CH]);
    float4* oto = reinterpret_cast<float4*>(&out[n * OUT_CH]);
    p2o[0] = make_float4(accl[0], accl[1], accl[2], accl[3]);
    p2o[1] = make_float4(accl[4], accl[5], accl[6], accl[7]);
    oto[0] = make_float4(accr[0], accr[1], accr[2], accr[3]);   // seed out = r2
    oto[1] = make_float4(accr[4], accr[5], accr[6], accr[7]);
}

// ---- K4: scatter2 directly into out: out[dst] += p2[src] * invd[dst] ------
__global__ void k4_scatter2(int n_edges, float* __restrict__ out) {
    int idx = blockIdx.x * B + threadIdx.x;
    int q4 = (idx & 1) * 4;
    cudaGridDependencySynchronize();   // wait for k3's p2/invd/out seed
    if (idx >= n_edges * 2) return;
    int pe = g_pedges[idx >> 1];               // broadcast within pair
    unsigned src = (unsigned)pe >> 16;
    unsigned dst = pe & 0xFFFF;
    float inv_d = g_invd[dst];                 // sink: 0.0 (never written)
    float4 v = *reinterpret_cast<const float4*>(&g_p2[src * OUT_CH + q4]);
    v.x *= inv_d; v.y *= inv_d; v.z *= inv_d; v.w *= inv_d;
    // branch-free target select: out has no sink row, use g_dummy instead
    float* tgt = (dst == N_NODES_MAX) ? &g_dummy[q4] : &out[dst * OUT_CH + q4];
    red_add_v4(tgt, v);
}

extern "C" void kernel_launch(void* const* d_in, const int* in_sizes, int n_in,
                              void* d_out, int out_size) {
    const float* x   = (const float*)d_in[0];
    const float* W1l = (const float*)d_in[1];
    const float* W1r = (const float*)d_in[2];
    const float* b1  = (const float*)d_in[3];
    const float* W2l = (const float*)d_in[4];
    const float* W2r = (const float*)d_in[5];
    const float* b2  = (const float*)d_in[6];
    const int*   ei  = (const int*)d_in[7];

    int n_nodes = in_sizes[0] / IN_CH;
    int n_edges = in_sizes[7] / 2;
    if (n_nodes > N_NODES_MAX) n_nodes = N_NODES_MAX;
    if (n_edges > N_EDGES_MAX) n_edges = N_EDGES_MAX;

    // K1: plain launch (consumes prior call's restored invariants).
    int g1 = (n_edges + B - 1) / B;            // covers decode; gemm grid-strides
    k1_gemm1_decode<<<g1, B>>>(x, W1l, W1r, b1, ei, n_nodes, n_edges, in_sizes[7]);

    // K2..K4: programmatic dependent launches.
    cudaLaunchAttribute attr[1];
    attr[0].id = cudaLaunchAttributeProgrammaticStreamSerialization;
    attr[0].val.programmaticStreamSerializationAllowed = 1;

    cudaLaunchConfig_t cfg = {};
    cfg.blockDim = dim3(B, 1, 1);
    cfg.attrs = attr;
    cfg.numAttrs = 1;
    cfg.stream = 0;

    cfg.gridDim = dim3((unsigned)((n_edges * 4 + B - 1) / B), 1, 1);
    cudaLaunchKernelEx(&cfg, k2_scatter1, n_edges);

    cfg.gridDim = dim3((unsigned)((n_nodes + B - 1) / B), 1, 1);
    cudaLaunchKernelEx(&cfg, k3_layer2, W2l, W2r, b2, n_nodes, (float*)d_out);

    cfg.gridDim = dim3((unsigned)((n_edges * 2 + B - 1) / B), 1, 1);
    cudaLaunchKernelEx(&cfg, k4_scatter2, n_edges, (float*)d_out);
}